// round 13
// baseline (speedup 1.0000x reference)
#include <cuda_runtime.h>
#include <cuda_fp16.h>
#include <cstdint>

#define N_I 500000
#define N_H 200000
#define F_I 32
#define F_H 16
#define EF  8
#define TPB 256

// Block counts per segment (threads = 256)
#define PREH_B 782     // ceil(200000/256)
#define PREI_B 1954    // ceil(500000/256)
#define E1_B   7813    // ceil(2000000/256)
#define E2_B   7813
#define FIN_B  489     // ceil(125000/256)  (float4 granularity)

// Packed per-source-node table entry: 32 bytes -> 1 L2 sector, one LDG.256.
__device__ __align__(32) uint4 g_tab_h[(size_t)N_H * 2];
__device__ __align__(32) uint4 g_tab_i[(size_t)N_I * 2];
// h2i messages accumulate here (out not yet initialized when edge1 runs).
__device__ __align__(16) float g_accum[N_I];   // zero at load; self-cleaned per run

// Readiness counters (zero at load; reset by the last finishing block).
__device__ int c_h, c_i, c_e1, c_fin;

__device__ __forceinline__ unsigned pack2(float a, float b) {
    __half2 h = __floats2half2_rn(a, b);
    return *reinterpret_cast<unsigned*>(&h);
}

__device__ __forceinline__ void spin_until(volatile int* ctr, int target) {
    if (threadIdx.x == 0) {
        while (*ctr < target) __nanosleep(128);
    }
    __syncthreads();
    __threadfence();   // acquire: producer data visible
}

__device__ __forceinline__ void signal(int* ctr) {
    __threadfence();   // release: make this block's stores visible first
    __syncthreads();
    if (threadIdx.x == 0) atomicAdd(ctr, 1);
}

// ---------------------------------------------------------------------------
// edge message: one LDG.256 ea stream + one LDG.256 table gather + atomic
// ---------------------------------------------------------------------------
__device__ __forceinline__ void edge_work(
    const float* __restrict__ ea, const int* __restrict__ src,
    const int* __restrict__ dst, const uint4* __restrict__ tab,
    float* __restrict__ acc, int e, int E)
{
    if (e >= E) return;

    int s = __ldcs(src + e);
    int d = __ldcs(dst + e);

    const void* eap = (const void*)(ea + (size_t)e * EF);
    unsigned a0, a1, a2, a3, a4, a5, a6, a7;
    asm volatile(
        "ld.global.cs.v8.b32 {%0,%1,%2,%3,%4,%5,%6,%7}, [%8];"
        : "=r"(a0), "=r"(a1), "=r"(a2), "=r"(a3),
          "=r"(a4), "=r"(a5), "=r"(a6), "=r"(a7)
        : "l"(eap));

    // .cg (L2-coherent) — table written earlier in the SAME launch.
    const void* tp = (const void*)(tab + (size_t)s * 2);
    unsigned r0, r1, r2, r3, r4, r5, r6, r7;
    asm volatile(
        "ld.global.cg.v8.b32 {%0,%1,%2,%3,%4,%5,%6,%7}, [%8];"
        : "=r"(r0), "=r"(r1), "=r"(r2), "=r"(r3),
          "=r"(r4), "=r"(r5), "=r"(r6), "=r"(r7)
        : "l"(tp));

    float2 f0 = __half22float2(*reinterpret_cast<__half2*>(&r0));
    float2 f1 = __half22float2(*reinterpret_cast<__half2*>(&r1));
    float2 f2 = __half22float2(*reinterpret_cast<__half2*>(&r2));
    float2 f3 = __half22float2(*reinterpret_cast<__half2*>(&r3));
    float  q  = __uint_as_float(r4);

    float msg = __uint_as_float(a0) * f0.x + __uint_as_float(a1) * f0.y
              + __uint_as_float(a2) * f1.x + __uint_as_float(a3) * f1.y
              + __uint_as_float(a4) * f2.x + __uint_as_float(a5) * f2.y
              + __uint_as_float(a6) * f3.x + __uint_as_float(a7) * f3.y + q;

    atomicAdd(acc + d, msg);
}

// ---------------------------------------------------------------------------
// ONE kernel, five block segments in dispatch order:
//   [0, PREH_B)                      : house precompute -> tab_h; c_h++
//   [PREH_B, +PREI_B)                : indivi precompute -> tab_i + out; c_i++
//   [.., +E1_B)                      : h2i edges (wait c_h)  -> g_accum; c_e1++
//   [.., +E2_B)                      : i2i edges (wait c_i)  -> out
//   [.., +FIN_B)                     : out += accum, accum = 0 (wait c_e1, c_i)
// In-order dispatch makes the waits deadlock-free; counters self-reset.
// ---------------------------------------------------------------------------
__global__ void mega_kernel(
    const float* __restrict__ x_i, const float* __restrict__ x_h,
    const float* __restrict__ W_i,  const float* __restrict__ b_i,
    const float* __restrict__ W_h,  const float* __restrict__ b_h,
    const float* __restrict__ wrh,  const float* __restrict__ wri,
    const float* __restrict__ bias_h, const float* __restrict__ bias_i,
    const float* __restrict__ ea1, const int* __restrict__ src1,
    const int* __restrict__ dst1, int E1,
    const float* __restrict__ ea2, const int* __restrict__ src2,
    const int* __restrict__ dst2, int E2,
    float* __restrict__ out)
{
    __shared__ float tile[TPB * 33];
    __shared__ float Ws[F_I * EF];
    __shared__ float bs[F_I];
    __shared__ float wr[F_I];

    const int tid = threadIdx.x;
    const int blk = blockIdx.x;

    if (blk < PREH_B) {
        // ================= house precompute =================
        for (int t = tid; t < F_H * EF; t += TPB) Ws[t] = W_h[t];
        if (tid < F_H) bs[tid] = b_h[tid];

        int base = blk * TPB;
        int cnt  = min(TPB, N_H - base);
        const float4* xg = (const float4*)x_h + (size_t)base * (F_H / 4);
        int total4 = cnt * (F_H / 4);
        for (int i = tid; i < total4; i += TPB) {
            float4 v = xg[i];
            float* dstp = tile + (i >> 2) * 17 + (i & 3) * 4;
            dstp[0] = v.x; dstp[1] = v.y; dstp[2] = v.z; dstp[3] = v.w;
        }
        __syncthreads();

        if (tid < cnt) {
            const float* xr = tile + tid * 17;
            float p[EF];
            #pragma unroll
            for (int k = 0; k < EF; k++) p[k] = 0.f;
            float q = 0.f;
            #pragma unroll
            for (int f = 0; f < F_H; f++) {
                float a = xr[f];
                q += a * bs[f];
                #pragma unroll
                for (int k = 0; k < EF; k++) p[k] += a * Ws[f * EF + k];
            }
            int n = base + tid;
            uint4 e0, e1v;
            e0.x = pack2(p[0], p[1]); e0.y = pack2(p[2], p[3]);
            e0.z = pack2(p[4], p[5]); e0.w = pack2(p[6], p[7]);
            e1v.x = __float_as_uint(q); e1v.y = 0; e1v.z = 0; e1v.w = 0;
            g_tab_h[(size_t)n * 2]     = e0;
            g_tab_h[(size_t)n * 2 + 1] = e1v;
        }
        signal(&c_h);
    } else if (blk < PREH_B + PREI_B) {
        // ================= indivi precompute + root-out =================
        for (int t = tid; t < F_I * EF; t += TPB) Ws[t] = W_i[t];
        if (tid < F_I) {
            bs[tid] = b_i[tid];
            wr[tid] = wrh[tid] + wri[tid];
        }

        int base = (blk - PREH_B) * TPB;
        int cnt  = min(TPB, N_I - base);
        const float4* xg = (const float4*)x_i + (size_t)base * (F_I / 4);
        int total4 = cnt * (F_I / 4);
        for (int i = tid; i < total4; i += TPB) {
            float4 v = xg[i];
            float* dstp = tile + (i >> 3) * 33 + (i & 7) * 4;
            dstp[0] = v.x; dstp[1] = v.y; dstp[2] = v.z; dstp[3] = v.w;
        }
        __syncthreads();

        if (tid < cnt) {
            const float* xr = tile + tid * 33;
            float p[EF];
            #pragma unroll
            for (int k = 0; k < EF; k++) p[k] = 0.f;
            float q = 0.f, r = 0.f;
            #pragma unroll
            for (int f = 0; f < F_I; f++) {
                float a = xr[f];
                q += a * bs[f];
                r += a * wr[f];
                #pragma unroll
                for (int k = 0; k < EF; k++) p[k] += a * Ws[f * EF + k];
            }
            int n = base + tid;
            uint4 e0, e1v;
            e0.x = pack2(p[0], p[1]); e0.y = pack2(p[2], p[3]);
            e0.z = pack2(p[4], p[5]); e0.w = pack2(p[6], p[7]);
            e1v.x = __float_as_uint(q); e1v.y = 0; e1v.z = 0; e1v.w = 0;
            g_tab_i[(size_t)n * 2]     = e0;
            g_tab_i[(size_t)n * 2 + 1] = e1v;
            out[n] = r + bias_h[0] + bias_i[0];
        }
        signal(&c_i);
    } else if (blk < PREH_B + PREI_B + E1_B) {
        // ================= h2i edges -> g_accum =================
        spin_until(&c_h, PREH_B);
        int e = (blk - PREH_B - PREI_B) * TPB + tid;
        edge_work(ea1, src1, dst1, g_tab_h, g_accum, e, E1);
        signal(&c_e1);
    } else if (blk < PREH_B + PREI_B + E1_B + E2_B) {
        // ================= i2i edges -> out =================
        spin_until(&c_i, PREI_B);
        int e = (blk - PREH_B - PREI_B - E1_B) * TPB + tid;
        edge_work(ea2, src2, dst2, g_tab_i, out, e, E2);
        __threadfence();
        __syncthreads();
        if (tid == 0) {
            int old = atomicAdd(&c_fin, 1);
            if (old == E2_B + FIN_B - 1) {
                c_h = 0; c_i = 0; c_e1 = 0;
                __threadfence();
                c_fin = 0;
            }
        }
    } else {
        // ================= final: out += accum; accum = 0 =================
        if (tid == 0) {
            volatile int* pe = &c_e1;
            volatile int* pi = &c_i;
            while (*pe < E1_B || *pi < PREI_B) __nanosleep(128);
        }
        __syncthreads();
        __threadfence();

        int i = (blk - PREH_B - PREI_B - E1_B - E2_B) * TPB + tid;
        if (i < N_I / 4) {
            float4* a4 = (float4*)g_accum;
            float4 v = a4[i];
            a4[i] = make_float4(0.f, 0.f, 0.f, 0.f);
            // edge2 atomics may still be in flight -> atomic add (commutative)
            atomicAdd(out + 4 * i + 0, v.x);
            atomicAdd(out + 4 * i + 1, v.y);
            atomicAdd(out + 4 * i + 2, v.z);
            atomicAdd(out + 4 * i + 3, v.w);
        }
        __threadfence();
        __syncthreads();
        if (tid == 0) {
            int old = atomicAdd(&c_fin, 1);
            if (old == E2_B + FIN_B - 1) {
                c_h = 0; c_i = 0; c_e1 = 0;
                __threadfence();
                c_fin = 0;
            }
        }
    }
}

extern "C" void kernel_launch(void* const* d_in, const int* in_sizes, int n_in,
                              void* d_out, int out_size)
{
    const float* x_indivi   = (const float*)d_in[0];
    const float* x_house    = (const float*)d_in[1];
    const float* ea_h2i     = (const float*)d_in[2];
    const float* ea_i2i     = (const float*)d_in[3];
    const float* W_edge_h2i = (const float*)d_in[4];
    const float* b_edge_h2i = (const float*)d_in[5];
    const float* W_edge_i2i = (const float*)d_in[6];
    const float* b_edge_i2i = (const float*)d_in[7];
    const float* W_root_h2i = (const float*)d_in[8];
    const float* bias_h2i   = (const float*)d_in[9];
    const float* W_root_i2i = (const float*)d_in[10];
    const float* bias_i2i   = (const float*)d_in[11];
    const int*   src_h2i    = (const int*)d_in[12];
    const int*   dst_h2i    = (const int*)d_in[13];
    const int*   src_i2i    = (const int*)d_in[14];
    const int*   dst_i2i    = (const int*)d_in[15];

    float* out = (float*)d_out;

    const int E1 = in_sizes[12];
    const int E2 = in_sizes[14];

    const int grid = PREH_B + PREI_B + E1_B + E2_B + FIN_B;
    mega_kernel<<<grid, TPB>>>(
        x_indivi, x_house,
        W_edge_i2i, b_edge_i2i, W_edge_h2i, b_edge_h2i,
        W_root_h2i, W_root_i2i, bias_h2i, bias_i2i,
        ea_h2i, src_h2i, dst_h2i, E1,
        ea_i2i, src_i2i, dst_i2i, E2,
        out);
}

// round 14
// speedup vs baseline: 1.9932x; 1.9932x over previous
#include <cuda_runtime.h>
#include <cuda_fp16.h>
#include <cstdint>

#define N_I 500000
#define N_H 200000
#define F_I 32
#define F_H 16
#define EF  8
#define TPB 256

// Packed per-source-node table entry: 32 bytes, 32B-aligned -> 1 L2 sector,
// fetched with a single 256-bit load in the edge kernel.
__device__ __align__(32) uint4 g_tab_h[(size_t)N_H * 2];
__device__ __align__(32) uint4 g_tab_i[(size_t)N_I * 2];

__device__ __forceinline__ unsigned pack2(float a, float b) {
    __half2 h = __floats2half2_rn(a, b);
    return *reinterpret_cast<unsigned*>(&h);
}

__device__ __forceinline__ float elem4(const float4& v, int j) {
    return j == 0 ? v.x : (j == 1 ? v.y : (j == 2 ? v.z : v.w));
}

// ---------------------------------------------------------------------------
// Kernel 1: one pass over node features, smem-staged, fully vectorized smem.
//   blocks [0, BI)      : indivi (256 nodes/block) -> tab_i + out root term
//   blocks [BI, BI+BH)  : house  (256 nodes/block) -> tab_h
// Tile rows: indivi 36 words (144B, 16B-aligned), house 20 words (80B).
// Both strides give conflict-free LDS.128 row reads (disjoint 4-bank spans
// per 8-lane phase). W is read as float4 broadcasts, (bs,wr) as one float2.
// Per-node LDS instruction count drops ~3.4x vs scalar version.
// ---------------------------------------------------------------------------
__global__ void fused_precompute_kernel(
    const float* __restrict__ x_i, const float* __restrict__ x_h,
    const float* __restrict__ W_i,  const float* __restrict__ b_i,
    const float* __restrict__ W_h,  const float* __restrict__ b_h,
    const float* __restrict__ wrh,  const float* __restrict__ wri,
    const float* __restrict__ bias_h, const float* __restrict__ bias_i,
    uint4* __restrict__ tab_i, uint4* __restrict__ tab_h,
    float* __restrict__ out, int BI)
{
    __shared__ __align__(16) float tile[TPB * 36];   // house reuses with stride 20
    __shared__ float4 Ws4[F_I * 2];                  // W rows as float4 pairs
    __shared__ float2 bw[F_I];                       // (b_edge, w_root) packed

    const int tid = threadIdx.x;

    if (blockIdx.x < BI) {
        // ================= indivi =================
        if (tid < F_I * 2) Ws4[tid] = ((const float4*)W_i)[tid];
        if (tid < F_I) bw[tid] = make_float2(b_i[tid], wrh[tid] + wri[tid]);

        int base = blockIdx.x * TPB;
        int cnt  = min(TPB, N_I - base);

        // Stage: cnt*8 float4, fully coalesced global reads.
        const float4* xg = (const float4*)x_i + (size_t)base * (F_I / 4);
        int total4 = cnt * (F_I / 4);
        for (int i = tid; i < total4; i += TPB) {
            float4 v = xg[i];
            *(float4*)(tile + (i >> 3) * 36 + (i & 7) * 4) = v;
        }
        __syncthreads();

        if (tid < cnt) {
            // 8 x LDS.128: whole x row into registers
            const float4* xr4 = (const float4*)(tile + tid * 36);
            float4 xv[8];
            #pragma unroll
            for (int f4 = 0; f4 < 8; f4++) xv[f4] = xr4[f4];

            float p[EF];
            #pragma unroll
            for (int k = 0; k < EF; k++) p[k] = 0.f;
            float q = 0.f, r = 0.f;

            #pragma unroll
            for (int f = 0; f < F_I; f++) {
                float a = elem4(xv[f >> 2], f & 3);
                float4 w0 = Ws4[f * 2];
                float4 w1 = Ws4[f * 2 + 1];
                float2 bwv = bw[f];
                q += a * bwv.x;
                r += a * bwv.y;
                p[0] += a * w0.x; p[1] += a * w0.y; p[2] += a * w0.z; p[3] += a * w0.w;
                p[4] += a * w1.x; p[5] += a * w1.y; p[6] += a * w1.z; p[7] += a * w1.w;
            }

            int n = base + tid;
            uint4 e0, e1;
            e0.x = pack2(p[0], p[1]); e0.y = pack2(p[2], p[3]);
            e0.z = pack2(p[4], p[5]); e0.w = pack2(p[6], p[7]);
            e1.x = __float_as_uint(q); e1.y = 0; e1.z = 0; e1.w = 0;
            tab_i[(size_t)n * 2]     = e0;
            tab_i[(size_t)n * 2 + 1] = e1;
            out[n] = r + bias_h[0] + bias_i[0];
        }
    } else {
        // ================= house =================
        if (tid < F_H * 2) Ws4[tid] = ((const float4*)W_h)[tid];
        if (tid < F_H) bw[tid] = make_float2(b_h[tid], 0.f);

        int base = (blockIdx.x - BI) * TPB;
        int cnt  = min(TPB, N_H - base);

        const float4* xg = (const float4*)x_h + (size_t)base * (F_H / 4);
        int total4 = cnt * (F_H / 4);
        for (int i = tid; i < total4; i += TPB) {
            float4 v = xg[i];
            *(float4*)(tile + (i >> 2) * 20 + (i & 3) * 4) = v;
        }
        __syncthreads();

        if (tid < cnt) {
            const float4* xr4 = (const float4*)(tile + tid * 20);
            float4 xv[4];
            #pragma unroll
            for (int f4 = 0; f4 < 4; f4++) xv[f4] = xr4[f4];

            float p[EF];
            #pragma unroll
            for (int k = 0; k < EF; k++) p[k] = 0.f;
            float q = 0.f;

            #pragma unroll
            for (int f = 0; f < F_H; f++) {
                float a = elem4(xv[f >> 2], f & 3);
                float4 w0 = Ws4[f * 2];
                float4 w1 = Ws4[f * 2 + 1];
                q += a * bw[f].x;
                p[0] += a * w0.x; p[1] += a * w0.y; p[2] += a * w0.z; p[3] += a * w0.w;
                p[4] += a * w1.x; p[5] += a * w1.y; p[6] += a * w1.z; p[7] += a * w1.w;
            }

            int n = base + tid;
            uint4 e0, e1;
            e0.x = pack2(p[0], p[1]); e0.y = pack2(p[2], p[3]);
            e0.z = pack2(p[4], p[5]); e0.w = pack2(p[6], p[7]);
            e1.x = __float_as_uint(q); e1.y = 0; e1.z = 0; e1.w = 0;
            tab_h[(size_t)n * 2]     = e0;
            tab_h[(size_t)n * 2 + 1] = e1;
        }
    }
}

// ---------------------------------------------------------------------------
// Kernel 2: both edge relations; one LDG.256 ea stream + one LDG.256 table
// gather + one atomic per edge. (measured 43.8-43.9us form, unchanged)
// ---------------------------------------------------------------------------
__device__ __forceinline__ void edge_work(
    const float* __restrict__ ea, const int* __restrict__ src,
    const int* __restrict__ dst, const uint4* __restrict__ tab,
    float* __restrict__ out, int e, int E)
{
    if (e >= E) return;

    int s = __ldcs(src + e);
    int d = __ldcs(dst + e);

    const void* eap = (const void*)(ea + (size_t)e * EF);
    unsigned a0, a1, a2, a3, a4, a5, a6, a7;
    asm volatile(
        "ld.global.cs.v8.b32 {%0,%1,%2,%3,%4,%5,%6,%7}, [%8];"
        : "=r"(a0), "=r"(a1), "=r"(a2), "=r"(a3),
          "=r"(a4), "=r"(a5), "=r"(a6), "=r"(a7)
        : "l"(eap));

    const void* tp = (const void*)(tab + (size_t)s * 2);
    unsigned r0, r1, r2, r3, r4, r5, r6, r7;
    asm volatile(
        "ld.global.nc.v8.b32 {%0,%1,%2,%3,%4,%5,%6,%7}, [%8];"
        : "=r"(r0), "=r"(r1), "=r"(r2), "=r"(r3),
          "=r"(r4), "=r"(r5), "=r"(r6), "=r"(r7)
        : "l"(tp));

    float2 f0 = __half22float2(*reinterpret_cast<__half2*>(&r0));
    float2 f1 = __half22float2(*reinterpret_cast<__half2*>(&r1));
    float2 f2 = __half22float2(*reinterpret_cast<__half2*>(&r2));
    float2 f3 = __half22float2(*reinterpret_cast<__half2*>(&r3));
    float  q  = __uint_as_float(r4);

    float msg = __uint_as_float(a0) * f0.x + __uint_as_float(a1) * f0.y
              + __uint_as_float(a2) * f1.x + __uint_as_float(a3) * f1.y
              + __uint_as_float(a4) * f2.x + __uint_as_float(a5) * f2.y
              + __uint_as_float(a6) * f3.x + __uint_as_float(a7) * f3.y + q;

    atomicAdd(out + d, msg);
}

__global__ void fused_edge_kernel(
    const float* __restrict__ ea1, const int* __restrict__ src1,
    const int* __restrict__ dst1, const uint4* __restrict__ tab1, int E1,
    const float* __restrict__ ea2, const int* __restrict__ src2,
    const int* __restrict__ dst2, const uint4* __restrict__ tab2, int E2,
    float* __restrict__ out, int B1)
{
    if (blockIdx.x < B1) {
        int e = blockIdx.x * blockDim.x + threadIdx.x;
        edge_work(ea1, src1, dst1, tab1, out, e, E1);
    } else {
        int e = (blockIdx.x - B1) * blockDim.x + threadIdx.x;
        edge_work(ea2, src2, dst2, tab2, out, e, E2);
    }
}

extern "C" void kernel_launch(void* const* d_in, const int* in_sizes, int n_in,
                              void* d_out, int out_size)
{
    const float* x_indivi   = (const float*)d_in[0];
    const float* x_house    = (const float*)d_in[1];
    const float* ea_h2i     = (const float*)d_in[2];
    const float* ea_i2i     = (const float*)d_in[3];
    const float* W_edge_h2i = (const float*)d_in[4];
    const float* b_edge_h2i = (const float*)d_in[5];
    const float* W_edge_i2i = (const float*)d_in[6];
    const float* b_edge_i2i = (const float*)d_in[7];
    const float* W_root_h2i = (const float*)d_in[8];
    const float* bias_h2i   = (const float*)d_in[9];
    const float* W_root_i2i = (const float*)d_in[10];
    const float* bias_i2i   = (const float*)d_in[11];
    const int*   src_h2i    = (const int*)d_in[12];
    const int*   dst_h2i    = (const int*)d_in[13];
    const int*   src_i2i    = (const int*)d_in[14];
    const int*   dst_i2i    = (const int*)d_in[15];

    float* out = (float*)d_out;

    const int E1 = in_sizes[12];
    const int E2 = in_sizes[14];

    uint4* tab_h = nullptr;
    uint4* tab_i = nullptr;
    cudaGetSymbolAddress((void**)&tab_h, g_tab_h);
    cudaGetSymbolAddress((void**)&tab_i, g_tab_i);

    // Kernel 1: fused precompute + root init (vectorized smem)
    {
        int BI = (N_I + TPB - 1) / TPB;   // 1954
        int BH = (N_H + TPB - 1) / TPB;   // 782
        fused_precompute_kernel<<<BI + BH, TPB>>>(
            x_indivi, x_house,
            W_edge_i2i, b_edge_i2i, W_edge_h2i, b_edge_h2i,
            W_root_h2i, W_root_i2i, bias_h2i, bias_i2i,
            tab_i, tab_h, out, BI);
    }
    // Kernel 2: both edge relations
    {
        int B1 = (E1 + TPB - 1) / TPB;
        int B2 = (E2 + TPB - 1) / TPB;
        fused_edge_kernel<<<B1 + B2, TPB>>>(
            ea_h2i, src_h2i, dst_h2i, tab_h, E1,
            ea_i2i, src_i2i, dst_i2i, tab_i, E2,
            out, B1);
    }
}